// round 15
// baseline (speedup 1.0000x reference)
#include <cuda_runtime.h>

#define BB   8
#define NN   9225
#define MM   4096
#define KNB  32
#define HID  64
#define DOUT 16

// ---- packed f32x2 helpers (sm_103a FFMA2 path, PTX-only) ----
typedef unsigned long long u64;
__device__ __forceinline__ u64 fmax2(u64 a, u64 b, u64 c) {
    u64 r;
    asm("fma.rn.f32x2 %0, %1, %2, %3;" : "=l"(r) : "l"(a), "l"(b), "l"(c));
    return r;
}
__device__ __forceinline__ u64 addx2(u64 a, u64 b) {
    u64 r;
    asm("add.rn.f32x2 %0, %1, %2;" : "=l"(r) : "l"(a), "l"(b));
    return r;
}
__device__ __forceinline__ u64 mulx2(u64 a, u64 b) {
    u64 r;
    asm("mul.rn.f32x2 %0, %1, %2;" : "=l"(r) : "l"(a), "l"(b));
    return r;
}
__device__ __forceinline__ u64 pack2(float lo, float hi) {
    u64 r;
    asm("mov.b64 %0, {%1, %2};" : "=l"(r) : "f"(lo), "f"(hi));
    return r;
}
__device__ __forceinline__ void unpack2(u64 v, float& lo, float& hi) {
    asm("mov.b64 {%0, %1}, %2;" : "=f"(lo), "=f"(hi) : "l"(v));
}
__device__ __forceinline__ u64 shfl64(u64 v, int off) {
    return __shfl_xor_sync(0xffffffffu, v, off);
}
__device__ __forceinline__ float rcp_approx(float x) {
    float r;
    asm("rcp.approx.f32 %0, %1;" : "=f"(r) : "f"(x));
    return r;
}
__device__ __forceinline__ float ex2_approx(float x) {
    float r;
    asm("ex2.approx.f32 %0, %1;" : "=f"(r) : "f"(x));
    return r;
}

__global__ __launch_bounds__(256) void it_kernel(
    const float* __restrict__ y,     // [B,N,2]
    const float* __restrict__ x,     // [B,M,2]
    const float* __restrict__ f_y,   // [B,N,16]
    const float* __restrict__ wts,   // [B,N]
    const float* __restrict__ W1,    // [4,64]
    const float* __restrict__ b1,    // [64]
    const float* __restrict__ W2,    // [64,16] read via LDG.128 (L1-resident)
    const float* __restrict__ b2,    // [16]
    const void*  __restrict__ nbr,   // [B,M,32] int64 or int32
    float* __restrict__ out)         // [B,M,16]
{
    // Per-warp layer-1 table, PRE-SCALED by 1/sqrt(2) and packed by hidden
    // pair (j, j+32): sW01 = {w0_j|w0_j32, w1_j|w1_j32}, sC = {c_j|c_j32},
    // c_j = b1_j + x0*W1[2][j] + x1*W1[3][j] (x warp-uniform).
    __shared__ __align__(16) ulonglong2 sW01[8][32];   // 4 KB
    __shared__ __align__(8)  u64        sC[8][32];     // 2 KB

    const int tid  = threadIdx.x;
    const int wb   = tid >> 5;
    const int lane = tid & 31;
    const int warp = (blockIdx.x << 3) + wb;   // global (b,m) id
    const int b    = warp / MM;

    // ---- inline index-width detection (every block reads the SAME first 32
    // high-word candidates -> identical decision in all blocks; int64 data has
    // hi-words only 0/-1, int32 data almost surely not) ----
    int badp = 0;
    if (tid < 32) {
        int hi = ((const int*)nbr)[2 * tid + 1];
        badp = (hi != 0 && hi != -1);
    }
    const bool is64 = (__syncthreads_or(badp) == 0);

    // ---- per-lane gather ----
    long long raw;
    if (is64) raw = ((const long long*)nbr)[(size_t)warp * KNB + lane];
    else      raw = (long long)((const int*)nbr)[(size_t)warp * KNB + lane];
    const bool valid = (raw >= 0);
    const int idx = valid ? (int)raw : 0;

    const float2 yy = ((const float2*)y)[(size_t)b * NN + idx];
    const float2 xx = ((const float2*)x)[warp];
    const float s = valid ? wts[(size_t)b * NN + idx] : 0.0f;

    // ---- build packed pre-scaled layer-1 table ----
    {
        const float ISQ2 = 0.70710678118654752f;
        const float a2 = xx.x, a3 = xx.y;
        int j0 = lane, j1 = lane + 32;
        float w0a = W1[j0] * ISQ2,          w0b = W1[j1] * ISQ2;
        float w1a = W1[HID + j0] * ISQ2,    w1b = W1[HID + j1] * ISQ2;
        float ca = fmaf(a3, W1[3 * HID + j0], fmaf(a2, W1[2 * HID + j0], b1[j0])) * ISQ2;
        float cb = fmaf(a3, W1[3 * HID + j1], fmaf(a2, W1[2 * HID + j1], b1[j1])) * ISQ2;
        ulonglong2 w01;
        w01.x = pack2(w0a, w0b);
        w01.y = pack2(w1a, w1b);
        sW01[wb][lane] = w01;
        sC[wb][lane] = pack2(ca, cb);
    }
    __syncthreads();

    // packed broadcast inputs / constants
    const u64 a0p  = pack2(yy.x, yy.x);
    const u64 a1p  = pack2(yy.y, yy.y);
    const u64 ONES = 0x3f8000003f800000ull;               // {1,1}
    const u64 CA   = pack2(0.47047f, 0.47047f);           // A-S 7.1.25 p
    const u64 NL2E = pack2(-1.4426950408889634f, -1.4426950408889634f);
    // negated 7.1.25 coeffs so r = fma(qt, e, 1) = 1 - P(t)*e
    const u64 QA3  = pack2(-0.7478556f, -0.7478556f);
    const u64 QA2  = pack2( 0.0958798f,  0.0958798f);
    const u64 QA1  = pack2(-0.3480242f, -0.3480242f);
    const u64 ABSM = 0x7fffffff7fffffffull;

    u64 acc2[8];
    #pragma unroll
    for (int p = 0; p < 8; p++) acc2[p] = 0ull;

    const ulonglong2* __restrict__ W2r = (const ulonglong2*)W2;  // 4 x 16B per row

    #pragma unroll 16
    for (int p = 0; p < 32; p++) {
        ulonglong2 w01 = sW01[wb][p];
        u64 cp = sC[wb][p];
        // h' = h/sqrt(2) = erf argument for hidden units (p, p+32)
        u64 hp = fmax2(a0p, w01.x, fmax2(a1p, w01.y, cp));
        // branchless A-S 7.1.25 erf, packed (abs err <= 2.5e-5)
        u64 ax  = hp & ABSM;                          // |x|
        u64 d   = fmax2(CA, ax, ONES);
        float dlo, dhi; unpack2(d, dlo, dhi);
        u64 t   = pack2(rcp_approx(dlo), rcp_approx(dhi));
        u64 aa  = mulx2(hp, hp);                      // x^2 (even: no abs)
        u64 arg = mulx2(aa, NL2E);
        float alo, ahi; unpack2(arg, alo, ahi);
        u64 e   = pack2(ex2_approx(alo), ex2_approx(ahi));
        u64 q   = fmax2(QA3, t, QA2);
        q = fmax2(q, t, QA1);
        u64 qt  = mulx2(q, t);                        // -P(t)
        u64 r   = fmax2(qt, e, ONES);                 // erf(|x|), in (0,1)
        // scaled gelu via EVEN-function fold: h'*erf(h') = |h'|*erf(|h'|),
        // so g' = h'(1+erf(h')) = fma(ax, r, hp) — no sign restore needed.
        u64 g   = fmax2(ax, r, hp);
        // split the pair back to two broadcast factors
        float glo, ghi; unpack2(g, glo, ghi);
        u64 gl = pack2(glo, glo);
        u64 gh = pack2(ghi, ghi);
        // layer 2: unit p and unit p+32 via LDG.128 (uniform addr, L1-hot;
        // LDG structural floor 4 cyc vs LDC 8 -> half the port serialization)
        const ulonglong2* wlo = &W2r[p * 4];
        const ulonglong2* whi = &W2r[(p + 32) * 4];
        ulonglong2 lA = wlo[0], lB = wlo[1], lC = wlo[2], lD = wlo[3];
        acc2[0] = fmax2(gl, lA.x, acc2[0]);
        acc2[1] = fmax2(gl, lA.y, acc2[1]);
        acc2[2] = fmax2(gl, lB.x, acc2[2]);
        acc2[3] = fmax2(gl, lB.y, acc2[3]);
        acc2[4] = fmax2(gl, lC.x, acc2[4]);
        acc2[5] = fmax2(gl, lC.y, acc2[5]);
        acc2[6] = fmax2(gl, lD.x, acc2[6]);
        acc2[7] = fmax2(gl, lD.y, acc2[7]);
        ulonglong2 hA = whi[0], hB = whi[1], hC = whi[2], hD = whi[3];
        acc2[0] = fmax2(gh, hA.x, acc2[0]);
        acc2[1] = fmax2(gh, hA.y, acc2[1]);
        acc2[2] = fmax2(gh, hB.x, acc2[2]);
        acc2[3] = fmax2(gh, hB.y, acc2[3]);
        acc2[4] = fmax2(gh, hC.x, acc2[4]);
        acc2[5] = fmax2(gh, hC.y, acc2[5]);
        acc2[6] = fmax2(gh, hD.x, acc2[6]);
        acc2[7] = fmax2(gh, hD.y, acc2[7]);
    }

    // ---- epilogue: (acc*ISQ2 + b2) * f_y[idx] * w[idx] * valid, packed ----
    {
        const ulonglong2* fyp = (const ulonglong2*)(f_y + ((size_t)b * NN + idx) * DOUT);
        const ulonglong2* b2p = (const ulonglong2*)b2;   // warp-uniform LDG, L1-hot
        const u64 ISQ2P = pack2(0.70710678118654752f, 0.70710678118654752f);
        u64 ss = pack2(s, s);
        #pragma unroll
        for (int q2 = 0; q2 < 4; q2++) {
            ulonglong2 fy = fyp[q2];
            ulonglong2 bq = b2p[q2];
            acc2[2 * q2 + 0] = mulx2(mulx2(fmax2(acc2[2 * q2 + 0], ISQ2P, bq.x), fy.x), ss);
            acc2[2 * q2 + 1] = mulx2(mulx2(fmax2(acc2[2 * q2 + 1], ISQ2P, bq.y), fy.y), ss);
        }
    }

    // ---- channel-splitting warp reduce (16 ch over 32 lanes) ----
    {
        bool hi = (lane & 16) != 0;
        #pragma unroll
        for (int p = 0; p < 4; p++) {
            u64 send = hi ? acc2[p]     : acc2[p + 4];
            u64 keep = hi ? acc2[p + 4] : acc2[p];
            acc2[p] = addx2(keep, shfl64(send, 16));
        }
    }
    {
        bool hi = (lane & 8) != 0;
        #pragma unroll
        for (int p = 0; p < 2; p++) {
            u64 send = hi ? acc2[p]     : acc2[p + 2];
            u64 keep = hi ? acc2[p + 2] : acc2[p];
            acc2[p] = addx2(keep, shfl64(send, 8));
        }
    }
    {
        bool hi = (lane & 4) != 0;
        u64 send = hi ? acc2[0] : acc2[1];
        u64 keep = hi ? acc2[1] : acc2[0];
        acc2[0] = addx2(keep, shfl64(send, 4));
    }
    float r;
    {
        float lo, hv;
        unpack2(acc2[0], lo, hv);
        bool hi = (lane & 2) != 0;
        float send = hi ? lo : hv;
        float keep = hi ? hv : lo;
        r = keep + __shfl_xor_sync(0xffffffffu, send, 2);
    }
    r += __shfl_xor_sync(0xffffffffu, r, 1);

    if ((lane & 1) == 0)
        out[(size_t)warp * DOUT + (lane >> 1)] = r;
}

extern "C" void kernel_launch(void* const* d_in, const int* in_sizes, int n_in,
                              void* d_out, int out_size) {
    const float* y   = (const float*)d_in[0];
    const float* x   = (const float*)d_in[1];
    const float* f_y = (const float*)d_in[2];
    const float* wts = (const float*)d_in[3];
    const float* W1  = (const float*)d_in[4];
    const float* b1  = (const float*)d_in[5];
    const float* W2  = (const float*)d_in[6];
    const float* b2  = (const float*)d_in[7];
    const void*  nbr = d_in[8];

    // no constant-memory staging: W2 read directly via LDG (one less graph node)
    it_kernel<<<4096, 256>>>(y, x, f_y, wts, W1, b1, W2, b2, nbr, (float*)d_out);
}

// round 16
// speedup vs baseline: 1.8520x; 1.8520x over previous
#include <cuda_runtime.h>

#define BB   8
#define NN   9225
#define MM   4096
#define KNB  32
#define HID  64
#define DOUT 16

__constant__ __align__(16) float cW2[HID * DOUT];   // 4 KB

// ---- packed f32x2 helpers (sm_103a FFMA2 path, PTX-only) ----
typedef unsigned long long u64;
__device__ __forceinline__ u64 fmax2(u64 a, u64 b, u64 c) {
    u64 r;
    asm("fma.rn.f32x2 %0, %1, %2, %3;" : "=l"(r) : "l"(a), "l"(b), "l"(c));
    return r;
}
__device__ __forceinline__ u64 addx2(u64 a, u64 b) {
    u64 r;
    asm("add.rn.f32x2 %0, %1, %2;" : "=l"(r) : "l"(a), "l"(b));
    return r;
}
__device__ __forceinline__ u64 mulx2(u64 a, u64 b) {
    u64 r;
    asm("mul.rn.f32x2 %0, %1, %2;" : "=l"(r) : "l"(a), "l"(b));
    return r;
}
__device__ __forceinline__ u64 pack2(float lo, float hi) {
    u64 r;
    asm("mov.b64 %0, {%1, %2};" : "=l"(r) : "f"(lo), "f"(hi));
    return r;
}
__device__ __forceinline__ void unpack2(u64 v, float& lo, float& hi) {
    asm("mov.b64 {%0, %1}, %2;" : "=f"(lo), "=f"(hi) : "l"(v));
}
__device__ __forceinline__ u64 shfl64(u64 v, int off) {
    return __shfl_xor_sync(0xffffffffu, v, off);
}
__device__ __forceinline__ float rcp_approx(float x) {
    float r;
    asm("rcp.approx.f32 %0, %1;" : "=f"(r) : "f"(x));
    return r;
}
__device__ __forceinline__ float ex2_approx(float x) {
    float r;
    asm("ex2.approx.f32 %0, %1;" : "=f"(r) : "f"(x));
    return r;
}

__global__ __launch_bounds__(256) void it_kernel(
    const float* __restrict__ y,     // [B,N,2]
    const float* __restrict__ x,     // [B,M,2]
    const float* __restrict__ f_y,   // [B,N,16]
    const float* __restrict__ wts,   // [B,N]
    const float* __restrict__ W1,    // [4,64]
    const float* __restrict__ b1,    // [64]
    const float* __restrict__ b2,    // [16]
    const void*  __restrict__ nbr,   // [B,M,32] int64 or int32
    float* __restrict__ out)         // [B,M,16]
{
    // Per-warp layer-1 table, PRE-SCALED by 1/sqrt(2) and packed by hidden
    // pair (j, j+32): sW01 = {w0_j|w0_j32, w1_j|w1_j32}, sC = {c_j|c_j32},
    // c_j = b1_j + x0*W1[2][j] + x1*W1[3][j] (x warp-uniform).
    __shared__ __align__(16) ulonglong2 sW01[8][32];   // 4 KB
    __shared__ __align__(8)  u64        sC[8][32];     // 2 KB

    const int tid  = threadIdx.x;
    const int wb   = tid >> 5;
    const int lane = tid & 31;
    const int warp = (blockIdx.x << 3) + wb;   // global (b,m) id
    const int b    = warp / MM;

    // ---- inline index-width detection (every block reads the SAME first 32
    // high-word candidates -> identical decision in all blocks; int64 data has
    // hi-words only 0/-1, int32 data almost surely not) ----
    int badp = 0;
    if (tid < 32) {
        int hi = ((const int*)nbr)[2 * tid + 1];
        badp = (hi != 0 && hi != -1);
    }
    const bool is64 = (__syncthreads_or(badp) == 0);

    // ---- per-lane gather ----
    long long raw;
    if (is64) raw = ((const long long*)nbr)[(size_t)warp * KNB + lane];
    else      raw = (long long)((const int*)nbr)[(size_t)warp * KNB + lane];
    const bool valid = (raw >= 0);
    const int idx = valid ? (int)raw : 0;

    const float2 yy = ((const float2*)y)[(size_t)b * NN + idx];
    const float2 xx = ((const float2*)x)[warp];
    const float s = valid ? wts[(size_t)b * NN + idx] : 0.0f;

    // ---- build packed pre-scaled layer-1 table ----
    {
        const float ISQ2 = 0.70710678118654752f;
        const float a2 = xx.x, a3 = xx.y;
        int j0 = lane, j1 = lane + 32;
        float w0a = W1[j0] * ISQ2,          w0b = W1[j1] * ISQ2;
        float w1a = W1[HID + j0] * ISQ2,    w1b = W1[HID + j1] * ISQ2;
        float ca = fmaf(a3, W1[3 * HID + j0], fmaf(a2, W1[2 * HID + j0], b1[j0])) * ISQ2;
        float cb = fmaf(a3, W1[3 * HID + j1], fmaf(a2, W1[2 * HID + j1], b1[j1])) * ISQ2;
        ulonglong2 w01;
        w01.x = pack2(w0a, w0b);
        w01.y = pack2(w1a, w1b);
        sW01[wb][lane] = w01;
        sC[wb][lane] = pack2(ca, cb);
    }
    __syncthreads();

    // packed broadcast inputs / constants
    const u64 a0p  = pack2(yy.x, yy.x);
    const u64 a1p  = pack2(yy.y, yy.y);
    const u64 ONES = 0x3f8000003f800000ull;               // {1,1}
    const u64 CA   = pack2(0.47047f, 0.47047f);           // A-S 7.1.25 p
    const u64 NL2E = pack2(-1.4426950408889634f, -1.4426950408889634f);
    // negated 7.1.25 coeffs so r = fma(qt, e, 1) = 1 - P(t)*e
    const u64 QA3  = pack2(-0.7478556f, -0.7478556f);
    const u64 QA2  = pack2( 0.0958798f,  0.0958798f);
    const u64 QA1  = pack2(-0.3480242f, -0.3480242f);
    const u64 ABSM = 0x7fffffff7fffffffull;

    u64 acc2[8];
    #pragma unroll
    for (int p = 0; p < 8; p++) acc2[p] = 0ull;

    #pragma unroll 16
    for (int p = 0; p < 32; p++) {
        ulonglong2 w01 = sW01[wb][p];
        u64 cp = sC[wb][p];
        // h' = h/sqrt(2) = erf argument for hidden units (p, p+32)
        u64 hp = fmax2(a0p, w01.x, fmax2(a1p, w01.y, cp));
        // branchless A-S 7.1.25 erf, packed (abs err <= 2.5e-5)
        u64 ax  = hp & ABSM;                          // |x|
        u64 d   = fmax2(CA, ax, ONES);
        float dlo, dhi; unpack2(d, dlo, dhi);
        u64 t   = pack2(rcp_approx(dlo), rcp_approx(dhi));
        u64 aa  = mulx2(hp, hp);                      // x^2 (even: no abs)
        u64 arg = mulx2(aa, NL2E);
        float alo, ahi; unpack2(arg, alo, ahi);
        u64 e   = pack2(ex2_approx(alo), ex2_approx(ahi));
        u64 q   = fmax2(QA3, t, QA2);
        q = fmax2(q, t, QA1);
        u64 qt  = mulx2(q, t);                        // -P(t)
        u64 r   = fmax2(qt, e, ONES);                 // erf(|x|), in (0,1)
        // scaled gelu via EVEN-function fold: h'*erf(h') = |h'|*erf(|h'|),
        // so g' = h'(1+erf(h')) = fma(ax, r, hp) — no sign restore needed.
        u64 g   = fmax2(ax, r, hp);
        // split the pair back to two broadcast factors
        float glo, ghi; unpack2(g, glo, ghi);
        u64 gl = pack2(glo, glo);
        u64 gh = pack2(ghi, ghi);
        // layer 2: unit p and unit p+32 from the constant port (best of the
        // three weight-stream ports measured: LDC 87us < LDS 94us < LDG 158us)
        const ulonglong2* wlo = (const ulonglong2*)&cW2[p * DOUT];
        const ulonglong2* whi = (const ulonglong2*)&cW2[(p + 32) * DOUT];
        ulonglong2 lA = wlo[0], lB = wlo[1], lC = wlo[2], lD = wlo[3];
        acc2[0] = fmax2(gl, lA.x, acc2[0]);
        acc2[1] = fmax2(gl, lA.y, acc2[1]);
        acc2[2] = fmax2(gl, lB.x, acc2[2]);
        acc2[3] = fmax2(gl, lB.y, acc2[3]);
        acc2[4] = fmax2(gl, lC.x, acc2[4]);
        acc2[5] = fmax2(gl, lC.y, acc2[5]);
        acc2[6] = fmax2(gl, lD.x, acc2[6]);
        acc2[7] = fmax2(gl, lD.y, acc2[7]);
        ulonglong2 hA = whi[0], hB = whi[1], hC = whi[2], hD = whi[3];
        acc2[0] = fmax2(gh, hA.x, acc2[0]);
        acc2[1] = fmax2(gh, hA.y, acc2[1]);
        acc2[2] = fmax2(gh, hB.x, acc2[2]);
        acc2[3] = fmax2(gh, hB.y, acc2[3]);
        acc2[4] = fmax2(gh, hC.x, acc2[4]);
        acc2[5] = fmax2(gh, hC.y, acc2[5]);
        acc2[6] = fmax2(gh, hD.x, acc2[6]);
        acc2[7] = fmax2(gh, hD.y, acc2[7]);
    }

    // ---- epilogue: (acc*ISQ2 + b2) * f_y[idx] * w[idx] * valid, packed ----
    {
        const ulonglong2* fyp = (const ulonglong2*)(f_y + ((size_t)b * NN + idx) * DOUT);
        const ulonglong2* b2p = (const ulonglong2*)b2;   // warp-uniform LDG, L1-hot
        const u64 ISQ2P = pack2(0.70710678118654752f, 0.70710678118654752f);
        u64 ss = pack2(s, s);
        #pragma unroll
        for (int q2 = 0; q2 < 4; q2++) {
            ulonglong2 fy = fyp[q2];
            ulonglong2 bq = b2p[q2];
            acc2[2 * q2 + 0] = mulx2(mulx2(fmax2(acc2[2 * q2 + 0], ISQ2P, bq.x), fy.x), ss);
            acc2[2 * q2 + 1] = mulx2(mulx2(fmax2(acc2[2 * q2 + 1], ISQ2P, bq.y), fy.y), ss);
        }
    }

    // ---- channel-splitting warp reduce (16 ch over 32 lanes) ----
    {
        bool hi = (lane & 16) != 0;
        #pragma unroll
        for (int p = 0; p < 4; p++) {
            u64 send = hi ? acc2[p]     : acc2[p + 4];
            u64 keep = hi ? acc2[p + 4] : acc2[p];
            acc2[p] = addx2(keep, shfl64(send, 16));
        }
    }
    {
        bool hi = (lane & 8) != 0;
        #pragma unroll
        for (int p = 0; p < 2; p++) {
            u64 send = hi ? acc2[p]     : acc2[p + 2];
            u64 keep = hi ? acc2[p + 2] : acc2[p];
            acc2[p] = addx2(keep, shfl64(send, 8));
        }
    }
    {
        bool hi = (lane & 4) != 0;
        u64 send = hi ? acc2[0] : acc2[1];
        u64 keep = hi ? acc2[1] : acc2[0];
        acc2[0] = addx2(keep, shfl64(send, 4));
    }
    float r;
    {
        float lo, hv;
        unpack2(acc2[0], lo, hv);
        bool hi = (lane & 2) != 0;
        float send = hi ? lo : hv;
        float keep = hi ? hv : lo;
        r = keep + __shfl_xor_sync(0xffffffffu, send, 2);
    }
    r += __shfl_xor_sync(0xffffffffu, r, 1);

    if ((lane & 1) == 0)
        out[(size_t)warp * DOUT + (lane >> 1)] = r;
}

extern "C" void kernel_launch(void* const* d_in, const int* in_sizes, int n_in,
                              void* d_out, int out_size) {
    const float* y   = (const float*)d_in[0];
    const float* x   = (const float*)d_in[1];
    const float* f_y = (const float*)d_in[2];
    const float* wts = (const float*)d_in[3];
    const float* W1  = (const float*)d_in[4];
    const float* b1  = (const float*)d_in[5];
    const float* W2  = (const float*)d_in[6];
    const float* b2  = (const float*)d_in[7];
    const void*  nbr = d_in[8];

    cudaMemcpyToSymbolAsync(cW2, W2, HID * DOUT * sizeof(float), 0,
                            cudaMemcpyDeviceToDevice, 0);

    it_kernel<<<4096, 256>>>(y, x, f_y, wts, W1, b1, b2, nbr, (float*)d_out);
}

// round 17
// speedup vs baseline: 2.2334x; 1.2059x over previous
#include <cuda_runtime.h>

#define BB   8
#define NN   9225
#define MM   4096
#define KNB  32
#define HID  64
#define DOUT 16

__constant__ __align__(16) float cW2[HID * DOUT];   // 4 KB

// ---- packed f32x2 helpers (sm_103a FFMA2 path, PTX-only) ----
typedef unsigned long long u64;
__device__ __forceinline__ u64 fmax2(u64 a, u64 b, u64 c) {
    u64 r;
    asm("fma.rn.f32x2 %0, %1, %2, %3;" : "=l"(r) : "l"(a), "l"(b), "l"(c));
    return r;
}
__device__ __forceinline__ u64 addx2(u64 a, u64 b) {
    u64 r;
    asm("add.rn.f32x2 %0, %1, %2;" : "=l"(r) : "l"(a), "l"(b));
    return r;
}
__device__ __forceinline__ u64 mulx2(u64 a, u64 b) {
    u64 r;
    asm("mul.rn.f32x2 %0, %1, %2;" : "=l"(r) : "l"(a), "l"(b));
    return r;
}
__device__ __forceinline__ u64 pack2(float lo, float hi) {
    u64 r;
    asm("mov.b64 %0, {%1, %2};" : "=l"(r) : "f"(lo), "f"(hi));
    return r;
}
__device__ __forceinline__ void unpack2(u64 v, float& lo, float& hi) {
    asm("mov.b64 {%0, %1}, %2;" : "=f"(lo), "=f"(hi) : "l"(v));
}
__device__ __forceinline__ u64 shfl64(u64 v, int off) {
    return __shfl_xor_sync(0xffffffffu, v, off);
}
__device__ __forceinline__ float ex2_approx(float x) {
    float r;
    asm("ex2.approx.f32 %0, %1;" : "=f"(r) : "f"(x));
    return r;
}

__global__ __launch_bounds__(256) void it_kernel(
    const float* __restrict__ y,     // [B,N,2]
    const float* __restrict__ x,     // [B,M,2]
    const float* __restrict__ f_y,   // [B,N,16]
    const float* __restrict__ wts,   // [B,N]
    const float* __restrict__ W1,    // [4,64]
    const float* __restrict__ b1,    // [64]
    const float* __restrict__ b2,    // [16]
    const void*  __restrict__ nbr,   // [B,M,32] int64 or int32
    float* __restrict__ out)         // [B,M,16]
{
    // Per-warp layer-1 table, PRE-SCALED by 1/sqrt(2) and packed by hidden
    // pair (j, j+32): sW01 = {w0_j|w0_j32, w1_j|w1_j32}, sC = {c_j|c_j32},
    // c_j = b1_j + x0*W1[2][j] + x1*W1[3][j] (x warp-uniform).
    __shared__ __align__(16) ulonglong2 sW01[8][32];   // 4 KB
    __shared__ __align__(8)  u64        sC[8][32];     // 2 KB

    const int tid  = threadIdx.x;
    const int wb   = tid >> 5;
    const int lane = tid & 31;
    const int warp = (blockIdx.x << 3) + wb;   // global (b,m) id
    const int b    = warp / MM;

    // ---- inline index-width detection (every block reads the SAME first 32
    // high-word candidates -> identical decision in all blocks; int64 data has
    // hi-words only 0/-1, int32 data almost surely not) ----
    int badp = 0;
    if (tid < 32) {
        int hi = ((const int*)nbr)[2 * tid + 1];
        badp = (hi != 0 && hi != -1);
    }
    const bool is64 = (__syncthreads_or(badp) == 0);

    // ---- per-lane gather ----
    long long raw;
    if (is64) raw = ((const long long*)nbr)[(size_t)warp * KNB + lane];
    else      raw = (long long)((const int*)nbr)[(size_t)warp * KNB + lane];
    const bool valid = (raw >= 0);
    const int idx = valid ? (int)raw : 0;

    const float2 yy = ((const float2*)y)[(size_t)b * NN + idx];
    const float2 xx = ((const float2*)x)[warp];
    const float s = valid ? wts[(size_t)b * NN + idx] : 0.0f;

    // ---- build packed pre-scaled layer-1 table ----
    {
        const float ISQ2 = 0.70710678118654752f;
        const float a2 = xx.x, a3 = xx.y;
        int j0 = lane, j1 = lane + 32;
        float w0a = W1[j0] * ISQ2,          w0b = W1[j1] * ISQ2;
        float w1a = W1[HID + j0] * ISQ2,    w1b = W1[HID + j1] * ISQ2;
        float ca = fmaf(a3, W1[3 * HID + j0], fmaf(a2, W1[2 * HID + j0], b1[j0])) * ISQ2;
        float cb = fmaf(a3, W1[3 * HID + j1], fmaf(a2, W1[2 * HID + j1], b1[j1])) * ISQ2;
        ulonglong2 w01;
        w01.x = pack2(w0a, w0b);
        w01.y = pack2(w1a, w1b);
        sW01[wb][lane] = w01;
        sC[wb][lane] = pack2(ca, cb);
    }
    __syncthreads();

    // packed broadcast inputs / constants
    const u64 a0p  = pack2(yy.x, yy.x);
    const u64 a1p  = pack2(yy.y, yy.y);
    const u64 ONES = 0x3f8000003f800000ull;               // {1,1}
    const u64 NEG1 = 0xbf800000bf800000ull;               // {-1,-1}
    // erfc(x) = 2^{-f(x)}, x>=0, with quartic f fit on [0,2.8]:
    //   f(x) = 1.62800x + 0.93320x^2 + 0.12035x^3 - 0.01324x^4
    // (slope-exact at 0; max erf abs err ~4e-4; extrapolates sanely to x=5).
    // Coefficients stored NEGATED so Horner yields -f = ex2 argument directly.
    const u64 QD = pack2( 0.01324f,  0.01324f);
    const u64 QC = pack2(-0.12035f, -0.12035f);
    const u64 QB = pack2(-0.93320f, -0.93320f);
    const u64 QA = pack2(-1.62800f, -1.62800f);
    const u64 ABSM = 0x7fffffff7fffffffull;

    u64 acc2[8];
    #pragma unroll
    for (int p = 0; p < 8; p++) acc2[p] = 0ull;

    #pragma unroll 16
    for (int p = 0; p < 32; p++) {
        ulonglong2 w01 = sW01[wb][p];
        u64 cp = sC[wb][p];
        // h' = h/sqrt(2) = erf argument for hidden units (p, p+32)
        u64 hp = fmax2(a0p, w01.x, fmax2(a1p, w01.y, cp));
        // ex2-only erf: erf(|x|) = 1 - 2^{-f(|x|)}  (2 MUFU, no rcp)
        u64 ax  = hp & ABSM;                          // |x|
        u64 pq  = fmax2(QD, ax, QC);                  // Horner for -f(|x|)
        pq = fmax2(pq, ax, QB);
        pq = fmax2(pq, ax, QA);
        u64 arg = mulx2(pq, ax);                      // -f(|x|) <= 0
        float alo, ahi; unpack2(arg, alo, ahi);
        u64 e   = pack2(ex2_approx(alo), ex2_approx(ahi));  // erfc(|x|)
        u64 r   = fmax2(e, NEG1, ONES);               // erf(|x|) = 1 - erfc
        // scaled gelu via EVEN-function fold: h'*erf(h') = |h'|*erf(|h'|),
        // so g' = h'(1+erf(h')) = fma(ax, r, hp) — no sign restore needed.
        u64 g   = fmax2(ax, r, hp);
        // split the pair back to two broadcast factors
        float glo, ghi; unpack2(g, glo, ghi);
        u64 gl = pack2(glo, glo);
        u64 gh = pack2(ghi, ghi);
        // layer 2: unit p and unit p+32 from the constant port (best of the
        // three weight-stream ports measured: LDC 87us < LDS 94us < LDG 158us)
        const ulonglong2* wlo = (const ulonglong2*)&cW2[p * DOUT];
        const ulonglong2* whi = (const ulonglong2*)&cW2[(p + 32) * DOUT];
        ulonglong2 lA = wlo[0], lB = wlo[1], lC = wlo[2], lD = wlo[3];
        acc2[0] = fmax2(gl, lA.x, acc2[0]);
        acc2[1] = fmax2(gl, lA.y, acc2[1]);
        acc2[2] = fmax2(gl, lB.x, acc2[2]);
        acc2[3] = fmax2(gl, lB.y, acc2[3]);
        acc2[4] = fmax2(gl, lC.x, acc2[4]);
        acc2[5] = fmax2(gl, lC.y, acc2[5]);
        acc2[6] = fmax2(gl, lD.x, acc2[6]);
        acc2[7] = fmax2(gl, lD.y, acc2[7]);
        ulonglong2 hA = whi[0], hB = whi[1], hC = whi[2], hD = whi[3];
        acc2[0] = fmax2(gh, hA.x, acc2[0]);
        acc2[1] = fmax2(gh, hA.y, acc2[1]);
        acc2[2] = fmax2(gh, hB.x, acc2[2]);
        acc2[3] = fmax2(gh, hB.y, acc2[3]);
        acc2[4] = fmax2(gh, hC.x, acc2[4]);
        acc2[5] = fmax2(gh, hC.y, acc2[5]);
        acc2[6] = fmax2(gh, hD.x, acc2[6]);
        acc2[7] = fmax2(gh, hD.y, acc2[7]);
    }

    // ---- epilogue: (acc*ISQ2 + b2) * f_y[idx] * w[idx] * valid, packed ----
    {
        const ulonglong2* fyp = (const ulonglong2*)(f_y + ((size_t)b * NN + idx) * DOUT);
        const ulonglong2* b2p = (const ulonglong2*)b2;   // warp-uniform LDG, L1-hot
        const u64 ISQ2P = pack2(0.70710678118654752f, 0.70710678118654752f);
        u64 ss = pack2(s, s);
        #pragma unroll
        for (int q2 = 0; q2 < 4; q2++) {
            ulonglong2 fy = fyp[q2];
            ulonglong2 bq = b2p[q2];
            acc2[2 * q2 + 0] = mulx2(mulx2(fmax2(acc2[2 * q2 + 0], ISQ2P, bq.x), fy.x), ss);
            acc2[2 * q2 + 1] = mulx2(mulx2(fmax2(acc2[2 * q2 + 1], ISQ2P, bq.y), fy.y), ss);
        }
    }

    // ---- channel-splitting warp reduce (16 ch over 32 lanes) ----
    {
        bool hi = (lane & 16) != 0;
        #pragma unroll
        for (int p = 0; p < 4; p++) {
            u64 send = hi ? acc2[p]     : acc2[p + 4];
            u64 keep = hi ? acc2[p + 4] : acc2[p];
            acc2[p] = addx2(keep, shfl64(send, 16));
        }
    }
    {
        bool hi = (lane & 8) != 0;
        #pragma unroll
        for (int p = 0; p < 2; p++) {
            u64 send = hi ? acc2[p]     : acc2[p + 2];
            u64 keep = hi ? acc2[p + 2] : acc2[p];
            acc2[p] = addx2(keep, shfl64(send, 8));
        }
    }
    {
        bool hi = (lane & 4) != 0;
        u64 send = hi ? acc2[0] : acc2[1];
        u64 keep = hi ? acc2[1] : acc2[0];
        acc2[0] = addx2(keep, shfl64(send, 4));
    }
    float r;
    {
        float lo, hv;
        unpack2(acc2[0], lo, hv);
        bool hi = (lane & 2) != 0;
        float send = hi ? lo : hv;
        float keep = hi ? hv : lo;
        r = keep + __shfl_xor_sync(0xffffffffu, send, 2);
    }
    r += __shfl_xor_sync(0xffffffffu, r, 1);

    if ((lane & 1) == 0)
        out[(size_t)warp * DOUT + (lane >> 1)] = r;
}

extern "C" void kernel_launch(void* const* d_in, const int* in_sizes, int n_in,
                              void* d_out, int out_size) {
    const float* y   = (const float*)d_in[0];
    const float* x   = (const float*)d_in[1];
    const float* f_y = (const float*)d_in[2];
    const float* wts = (const float*)d_in[3];
    const float* W1  = (const float*)d_in[4];
    const float* b1  = (const float*)d_in[5];
    const float* W2  = (const float*)d_in[6];
    const float* b2  = (const float*)d_in[7];
    const void*  nbr = d_in[8];

    cudaMemcpyToSymbolAsync(cW2, W2, HID * DOUT * sizeof(float), 0,
                            cudaMemcpyDeviceToDevice, 0);

    it_kernel<<<4096, 256>>>(y, x, f_y, wts, W1, b1, b2, nbr, (float*)d_out);
}